// round 10
// baseline (speedup 1.0000x reference)
#include <cuda_runtime.h>
#include <cuda_fp16.h>
#include <mma.h>
#include <math.h>
#include <cstdint>

using namespace nvcuda;

// ---------------- problem constants ----------------
#define Bb   8
#define Ss   920
#define Dd   1536
#define Hh   4
#define HDd  384
#define Ll   1839
#define BH   32
#define MQ   29440
#define HALFL 919
#define RST  2048                 // padded R row stride (halfs)
#define SROW 1024                 // padded scores row stride (fp32)
#define SZSTR (1024*1024)         // padded scores per-bh slab
#define WN3  (Dd*Hh*HDd)

// ---------------- GEMM tiling ----------------
#define BM 128
#define TK 64                     // k-depth per stage (halfs)
#define NSTAGE 3
#define NTHREADS 256
#define LDA 72                    // TK + 8 skew (halfs)

// ---------------- scratch ----------------
__device__ __half g_q[BH * Ss * HDd];
__device__ __half g_k[BH * Ss * HDd];
__device__ __half g_vt[BH * HDd * Ss];            // V^T: [bh][d][s]
__device__ __half g_r[(long long)MQ * RST];       // rel bias, HALF, padded
__device__ float  g_s[(long long)BH * SZSTR];     // scores fp32, padded slabs
__device__ __half g_p[(long long)BH * Ss * Ss];   // probs half, packed
__device__ __half g_hs[Bb * Ss * Dd];
__device__ __half g_wt[3 * WN3];                  // W^T half
__device__ __half g_de[Ll * HDd];

// ---------------- helpers ----------------
__device__ __forceinline__ uint32_t smem_u32(const void* p) {
    uint32_t a;
    asm("{ .reg .u64 t; cvta.to.shared.u64 t, %1; cvt.u32.u64 %0, t; }" : "=r"(a) : "l"(p));
    return a;
}
__device__ __forceinline__ void cp16s(uint32_t dst, const void* src, bool p) {
    int sz = p ? 16 : 0;
    asm volatile("cp.async.cg.shared.global [%0], [%1], 16, %2;\n" :: "r"(dst), "l"(src), "r"(sz));
}
__device__ __forceinline__ void cp_commit() { asm volatile("cp.async.commit_group;\n"); }
__device__ __forceinline__ void cp_wait0()  { asm volatile("cp.async.wait_group 0;\n"); }
__device__ __forceinline__ void cp_wait1()  { asm volatile("cp.async.wait_group 1;\n"); }

// ---------------- prep kernels ----------------
__global__ __launch_bounds__(256)
void f2h_copy(const float4* __restrict__ src, uint2* __restrict__ dst, int n4)
{
    int i = blockIdx.x * 256 + threadIdx.x;
    int st = gridDim.x * 256;
    for (; i < n4; i += st) {
        float4 v = src[i];
        __half2 h01 = __floats2half2_rn(v.x, v.y);
        __half2 h23 = __floats2half2_rn(v.z, v.w);
        uint2 o;
        o.x = *reinterpret_cast<uint32_t*>(&h01);
        o.y = *reinterpret_cast<uint32_t*>(&h23);
        dst[i] = o;
    }
}

// fused: all three W (1536x1536) -> W^T half slabs; z selects matrix
__global__ __launch_bounds__(256)
void transpose_h3(const float* __restrict__ w0, const float* __restrict__ w1,
                  const float* __restrict__ w2, __half* __restrict__ dst)
{
    __shared__ float t[32][33];
    const int z = blockIdx.z;
    const float* src = (z == 0) ? w0 : (z == 1) ? w1 : w2;
    __half* d = dst + (long long)z * WN3;
    int tx = threadIdx.x, ty = threadIdx.y;
    int x = blockIdx.x * 32 + tx;
    int y0 = blockIdx.y * 32;
    #pragma unroll
    for (int i = 0; i < 32; i += 8)
        t[ty + i][tx] = src[(long long)(y0 + ty + i) * 1536 + x];
    __syncthreads();
    int x2 = blockIdx.y * 32 + tx;
    int y2 = blockIdx.x * 32;
    #pragma unroll
    for (int i = 0; i < 32; i += 8)
        d[(long long)(y2 + ty + i) * 1536 + x2] = __float2half_rn(t[tx][ty + i]);
}

// =======================================================================
// fp16 WMMA NT GEMM: C = A(MxK,row,half) * B(NxK,row,half)^T, fp32 accum.
// CTA BM x BNV, 8 warps (2x4), warp tile 64 x (BNV/4). 3-stage, TK=64.
// BNV=256 -> warp tile 64x64, 0.087 B/MAC smem traffic, 1 CTA/SM
// BNV=128 -> warp tile 64x32, 2 CTAs/SM (MINB=2)
// EPI 0: fp32 direct store_matrix_sync, padded strides, no guard
// EPI 1: fused QKV (z: 0->Cv(q),1->C1(k),2->C2(vt)); scale only z==0
// EPI 2: ctx: z=(b,h): fp32 out[(b*S+gm)*1536 + h*384 + gn], guarded
// EPI 3: half output, padded row stride ldC, no guard (R)
// BAND: early-exit for R band
// =======================================================================
template<int BNV, int EPI, bool BAND, int MINB>
__global__ __launch_bounds__(NTHREADS, MINB)
void gemm_h(const __half* __restrict__ A, const __half* __restrict__ B,
            void* __restrict__ Cv,
            int M, int N, int K,
            long long strA, long long strB, long long strC, int ldC,
            float scale, __half* __restrict__ C1, __half* __restrict__ C2)
{
    constexpr int WNv = BNV / 4;          // 64 or 32
    constexpr int NF  = WNv / 16;         // 4 or 2
    constexpr int A_BYTES = BM * LDA * 2;
    constexpr int B_BYTES = BNV * LDA * 2;
    constexpr int STAGE_BYTES = A_BYTES + B_BYTES;
    constexpr int LDC = BNV + 4;

    const int m0 = blockIdx.y * BM;
    const int n0 = blockIdx.x * BNV;

    if (BAND) {
        int mq0 = m0 % Ss;
        int qlo, qhi;
        if (mq0 + (BM - 1) < Ss) { qlo = mq0; qhi = mq0 + BM - 1; }
        else                     { qlo = 0;   qhi = Ss - 1; }
        int lmin = HALFL - qhi, lmax = (Ll - 1) - qlo;
        if (n0 > lmax || n0 + BNV - 1 < lmin) return;
    }

    extern __shared__ char smem[];
    const uint32_t sb = smem_u32(smem);

    const int tid  = threadIdx.x;
    const int warp = tid >> 5;
    const int wm   = warp >> 2;
    const int wn   = warp & 3;
    const int z    = blockIdx.z;

    A += (long long)z * strA;
    B += (long long)z * strB;
    if (EPI == 1 && z != 0) scale = 1.0f;

    const int nIter = (K + TK - 1) / TK;

    wmma::fragment<wmma::accumulator, 16, 16, 16, float> acc[4][NF];
    #pragma unroll
    for (int i = 0; i < 4; i++)
        #pragma unroll
        for (int j = 0; j < NF; j++)
            wmma::fill_fragment(acc[i][j], 0.0f);

    auto issue_stage = [&](int s) {
        const uint32_t base = sb + (uint32_t)(s % NSTAGE) * STAGE_BYTES;
        const int k0 = s * TK;
        // A tile: BM x 64 halfs = BM*8 16B-chunks
        #pragma unroll
        for (int t = 0; t < BM * 8 / NTHREADS; t++) {
            int idx = tid + t * NTHREADS;
            int r = idx >> 3, c = idx & 7;
            int gm = m0 + r, gk = k0 + c * 8;
            bool p = (gm < M) && (gk < K);
            const __half* src = A + (long long)(p ? gm : 0) * K + (p ? gk : 0);
            cp16s(base + (uint32_t)(r * (LDA * 2) + c * 16), src, p);
        }
        // B tile: BNV x 64 halfs
        #pragma unroll
        for (int t = 0; t < BNV * 8 / NTHREADS; t++) {
            int idx = tid + t * NTHREADS;
            int r = idx >> 3, c = idx & 7;
            int gn = n0 + r, gk = k0 + c * 8;
            bool p = (gn < N) && (gk < K);
            const __half* src = B + (long long)(p ? gn : 0) * K + (p ? gk : 0);
            cp16s(base + (uint32_t)A_BYTES + (uint32_t)(r * (LDA * 2) + c * 16), src, p);
        }
        cp_commit();
    };

    issue_stage(0);
    issue_stage(1);

    for (int it = 0; it < nIter; ++it) {
        const __half* cA = (const __half*)(smem + (it % NSTAGE) * STAGE_BYTES);
        const __half* cB = (const __half*)(smem + (it % NSTAGE) * STAGE_BYTES + A_BYTES);

        if (it + 1 < nIter) cp_wait1(); else cp_wait0();
        __syncthreads();
        if (it + 2 < nIter) issue_stage(it + 2);

        #pragma unroll
        for (int kk = 0; kk < TK; kk += 16) {
            wmma::fragment<wmma::matrix_a, 16, 16, 16, __half, wmma::row_major> af[4];
            #pragma unroll
            for (int i = 0; i < 4; i++)
                wmma::load_matrix_sync(af[i], cA + (wm * 64 + i * 16) * LDA + kk, LDA);
            wmma::fragment<wmma::matrix_b, 16, 16, 16, __half, wmma::col_major> bf[NF];
            #pragma unroll
            for (int j = 0; j < NF; j++)
                wmma::load_matrix_sync(bf[j], cB + (wn * WNv + j * 16) * LDA + kk, LDA);
            #pragma unroll
            for (int i = 0; i < 4; i++)
                #pragma unroll
                for (int j = 0; j < NF; j++)
                    wmma::mma_sync(acc[i][j], af[i], bf[j], acc[i][j]);
        }
    }

    if (EPI == 0) {
        float* Cg = (float*)Cv + (long long)z * strC;
        #pragma unroll
        for (int i = 0; i < 4; i++) {
            int gm = m0 + wm * 64 + i * 16;
            #pragma unroll
            for (int j = 0; j < NF; j++) {
                int gn = n0 + wn * WNv + j * 16;
                wmma::store_matrix_sync(Cg + (long long)gm * ldC + gn,
                                        acc[i][j], ldC, wmma::mem_row_major);
            }
        }
        return;
    }

    __syncthreads();
    float* shC = (float*)smem;   // [BM][LDC]
    #pragma unroll
    for (int i = 0; i < 4; i++)
        #pragma unroll
        for (int j = 0; j < NF; j++)
            wmma::store_matrix_sync(&shC[(wm * 64 + i * 16) * LDC + (wn * WNv + j * 16)],
                                    acc[i][j], LDC, wmma::mem_row_major);
    __syncthreads();

    if (EPI == 3) {
        __half* Cg = (__half*)Cv;
        #pragma unroll 4
        for (int idx = tid; idx < BM * BNV; idx += NTHREADS) {
            int i = idx / BNV, j = idx % BNV;
            Cg[(long long)(m0 + i) * ldC + (n0 + j)] = __float2half_rn(shC[i * LDC + j]);
        }
    } else if (EPI == 1 && z == 2) {
        // V^T into C2: iterate m fast for coalesced s-dim stores
        #pragma unroll 4
        for (int idx = tid; idx < BM * BNV; idx += NTHREADS) {
            int i = idx % BM, j = idx / BM;
            int gm = m0 + i, gn = n0 + j;
            if (gm >= M || gn >= N) continue;
            float v = shC[i * LDC + j];
            int b2 = gm / Ss, sP = gm - b2 * Ss;
            int h = gn / HDd, d = gn - h * HDd;
            C2[(((long long)(b2 * Hh + h)) * HDd + d) * Ss + sP] = __float2half_rn(v);
        }
    } else {
        #pragma unroll 4
        for (int idx = tid; idx < BM * BNV; idx += NTHREADS) {
            int i = idx / BNV, j = idx % BNV;
            int gm = m0 + i, gn = n0 + j;
            if (gm >= M || gn >= N) continue;
            float v = shC[i * LDC + j] * scale;
            if (EPI == 1) {
                int b2 = gm / Ss, sP = gm - b2 * Ss;
                int h = gn / HDd, d = gn - h * HDd;
                __half hv = __float2half_rn(v);
                long long o = (((long long)(b2 * Hh + h)) * Ss + sP) * HDd + d;
                if (z == 0) ((__half*)Cv)[o] = hv; else C1[o] = hv;
            } else { // EPI == 2
                int b2 = z >> 2, h = z & 3;
                ((float*)Cv)[((long long)b2 * Ss + gm) * (Hh * HDd) + h * HDd + gn] = v;
            }
        }
    }
}

// =======================================================================
// bias + softmax: scores[bh,q,k] += R_half[m, k-q+919]; softmax; half probs
// =======================================================================
__global__ __launch_bounds__(256)
void bias_softmax(const float* __restrict__ sc, const __half* __restrict__ R,
                  __half* __restrict__ P)
{
    const int r = blockIdx.x;
    const int bh = r / Ss, q = r - bh * Ss;
    const float* row = sc + (long long)bh * SZSTR + (long long)q * SROW;
    const __half* rrow = R + (long long)r * RST + (HALFL - q);
    __half* prow = P + (long long)r * Ss;

    const int tid = threadIdx.x, lane = tid & 31, wid = tid >> 5;
    __shared__ float wred[8];

    float vals[4];
    float mx = -1e30f;
    #pragma unroll
    for (int i = 0; i < 4; i++) {
        int k = tid + i * 256;
        float v = -1e30f;
        if (k < Ss) v = row[k] + __half2float(rrow[k]);
        vals[i] = v;
        mx = fmaxf(mx, v);
    }
    #pragma unroll
    for (int o = 16; o > 0; o >>= 1) mx = fmaxf(mx, __shfl_xor_sync(0xffffffffu, mx, o));
    if (lane == 0) wred[wid] = mx;
    __syncthreads();
    mx = wred[0];
    #pragma unroll
    for (int w = 1; w < 8; w++) mx = fmaxf(mx, wred[w]);
    __syncthreads();

    float sum = 0.0f;
    #pragma unroll
    for (int i = 0; i < 4; i++) {
        int k = tid + i * 256;
        float e = 0.0f;
        if (k < Ss) e = __expf(vals[i] - mx);
        vals[i] = e;
        sum += e;
    }
    #pragma unroll
    for (int o = 16; o > 0; o >>= 1) sum += __shfl_xor_sync(0xffffffffu, sum, o);
    if (lane == 0) wred[wid] = sum;
    __syncthreads();
    sum = 0.0f;
    #pragma unroll
    for (int w = 0; w < 8; w++) sum += wred[w];

    const float inv = 1.0f / sum;
    #pragma unroll
    for (int i = 0; i < 4; i++) {
        int k = tid + i * 256;
        if (k < Ss) prow[k] = __float2half_rn(vals[i] * inv);
    }
}

// =======================================================================
extern "C" void kernel_launch(void* const* d_in, const int* in_sizes, int n_in,
                              void* d_out, int out_size)
{
    (void)in_sizes; (void)n_in; (void)out_size;
    const float* hs = (const float*)d_in[0];
    const float* wq = (const float*)d_in[1];
    const float* wk = (const float*)d_in[2];
    const float* wv = (const float*)d_in[3];
    const float* de = (const float*)d_in[4];
    float* out = (float*)d_out;

    __half *q, *k, *vt, *p, *hsr, *wt, *der, *r;
    float *s;
    cudaGetSymbolAddress((void**)&q,   g_q);
    cudaGetSymbolAddress((void**)&k,   g_k);
    cudaGetSymbolAddress((void**)&vt,  g_vt);
    cudaGetSymbolAddress((void**)&r,   g_r);
    cudaGetSymbolAddress((void**)&s,   g_s);
    cudaGetSymbolAddress((void**)&p,   g_p);
    cudaGetSymbolAddress((void**)&hsr, g_hs);
    cudaGetSymbolAddress((void**)&wt,  g_wt);
    cudaGetSymbolAddress((void**)&der, g_de);

    const int stage256 = NSTAGE * ((BM + 256) * LDA * 2);           // 165888
    const int stage128 = NSTAGE * ((BM + 128) * LDA * 2);           // 110592
    cudaFuncSetAttribute((const void*)gemm_h<256, 1, false, 1>, cudaFuncAttributeMaxDynamicSharedMemorySize, stage256);
    cudaFuncSetAttribute((const void*)gemm_h<256, 3, true,  1>, cudaFuncAttributeMaxDynamicSharedMemorySize, stage256);
    cudaFuncSetAttribute((const void*)gemm_h<256, 0, false, 1>, cudaFuncAttributeMaxDynamicSharedMemorySize, stage256);
    cudaFuncSetAttribute((const void*)gemm_h<128, 2, false, 2>, cudaFuncAttributeMaxDynamicSharedMemorySize, stage128);

    const float inv = 1.0f / sqrtf((float)HDd);
    dim3 blk(NTHREADS);

    // 0) prep
    f2h_copy<<<512, 256>>>((const float4*)hs, (uint2*)hsr, (Bb * Ss * Dd) / 4);
    f2h_copy<<<128, 256>>>((const float4*)de, (uint2*)der, (Ll * HDd) / 4);
    transpose_h3<<<dim3(48, 48, 3), dim3(32, 8)>>>(wq, wk, wv, wt);

    // 1) fused QKV: CTA 128x256, warp tile 64x64
    dim3 gA(Dd / 256, (Bb * Ss + BM - 1) / BM, 3);                  // (6, 58, 3)
    gemm_h<256, 1, false, 1><<<gA, blk, stage256>>>(hsr, wt, q, Bb * Ss, Hh * HDd, Dd,
                                                    0, (long long)WN3, 0, 0, inv, k, vt);

    // 2) R = Q @ DE^T (banded) -> half, stride RST, unguarded padded stores
    dim3 gR((Ll + 255) / 256, MQ / BM, 1);                          // (8, 230)
    gemm_h<256, 3, true, 1><<<gR, blk, stage256>>>(q, der, r, MQ, Ll, HDd,
                                                   0, 0, 0, RST, 1.0f, nullptr, nullptr);

    // 3) scores = Q @ K^T per bh -> fp32 padded slabs, direct stores
    dim3 gS(4, 8, BH);                                              // 1024x1024 padded
    gemm_h<256, 0, false, 1><<<gS, blk, stage256>>>(q, k, s, Ss, Ss, HDd,
                                                    (long long)Ss * HDd, (long long)Ss * HDd,
                                                    (long long)SZSTR, SROW, 1.0f, nullptr, nullptr);

    // 4) bias + softmax -> half probs
    bias_softmax<<<MQ, 256>>>(s, r, p);

    // 5) ctx = P @ Vt^T per bh -> fp32 (B,S,H*HD)
    dim3 gO(HDd / 128, (Ss + BM - 1) / BM, BH);                     // (3, 8, 32)
    gemm_h<128, 2, false, 2><<<gO, blk, stage128>>>(p, vt, out, Ss, HDd, Ss,
                                                    (long long)Ss * Ss, (long long)HDd * Ss,
                                                    0, 0, 1.0f, nullptr, nullptr);
}

// round 11
// speedup vs baseline: 1.1293x; 1.1293x over previous
#include <cuda_runtime.h>
#include <cuda_fp16.h>
#include <mma.h>
#include <math.h>
#include <cstdint>

using namespace nvcuda;

// ---------------- problem constants ----------------
#define Bb   8
#define Ss   920
#define Dd   1536
#define Hh   4
#define HDd  384
#define Ll   1839
#define BH   32
#define MQ   29440
#define HALFL 919
#define RST  2048                 // padded R row stride (halfs)
#define SROW 1024                 // padded scores row stride (fp32)
#define SZSTR (1024*1024)         // padded scores per-bh slab
#define WN3  (Dd*Hh*HDd)

// ---------------- GEMM tiling (R9 config: best known) ----------------
#define BM 128
#define BNV 128
#define TK 64                     // k-depth per stage (halfs)
#define NSTAGE 3
#define NTHREADS 256
#define LDA 72                    // TK + 8 skew (halfs)

// R/scores fused-launch grid bookkeeping
#define R_GX 15
#define R_GY 230
#define NR_CTAS (R_GX * R_GY)     // 3450
#define NS_CTAS (8 * 8 * BH)      // 2048

// ---------------- scratch ----------------
__device__ __half g_q[BH * Ss * HDd];
__device__ __half g_k[BH * Ss * HDd];
__device__ __half g_vt[BH * HDd * Ss];            // V^T: [bh][d][s]
__device__ __half g_r[(long long)MQ * RST];       // rel bias, HALF, padded
__device__ float  g_s[(long long)BH * SZSTR];     // scores fp32, padded slabs
__device__ __half g_p[(long long)BH * Ss * Ss];   // probs half, packed
__device__ __half g_hs[Bb * Ss * Dd];
__device__ __half g_wt[3 * WN3];                  // W^T half
__device__ __half g_de[Ll * HDd];

// ---------------- helpers ----------------
__device__ __forceinline__ uint32_t smem_u32(const void* p) {
    uint32_t a;
    asm("{ .reg .u64 t; cvta.to.shared.u64 t, %1; cvt.u32.u64 %0, t; }" : "=r"(a) : "l"(p));
    return a;
}
__device__ __forceinline__ void cp16s(uint32_t dst, const void* src, bool p) {
    int sz = p ? 16 : 0;
    asm volatile("cp.async.cg.shared.global [%0], [%1], 16, %2;\n" :: "r"(dst), "l"(src), "r"(sz));
}
__device__ __forceinline__ void cp_commit() { asm volatile("cp.async.commit_group;\n"); }
__device__ __forceinline__ void cp_wait0()  { asm volatile("cp.async.wait_group 0;\n"); }
__device__ __forceinline__ void cp_wait1()  { asm volatile("cp.async.wait_group 1;\n"); }

// ---------------- prep kernels ----------------
__global__ __launch_bounds__(256)
void f2h_copy2(const float4* __restrict__ s0, uint2* __restrict__ d0, int n0,
               const float4* __restrict__ s1, uint2* __restrict__ d1, int n1)
{
    int i = blockIdx.x * 256 + threadIdx.x;
    int st = gridDim.x * 256;
    for (; i < n0 + n1; i += st) {
        const float4* s = (i < n0) ? s0 : s1;
        uint2* d = (i < n0) ? d0 : d1;
        int idx = (i < n0) ? i : (i - n0);
        float4 v = s[idx];
        __half2 h01 = __floats2half2_rn(v.x, v.y);
        __half2 h23 = __floats2half2_rn(v.z, v.w);
        uint2 o;
        o.x = *reinterpret_cast<uint32_t*>(&h01);
        o.y = *reinterpret_cast<uint32_t*>(&h23);
        d[idx] = o;
    }
}

// fused: all three W (1536x1536) -> W^T half slabs; z selects matrix
__global__ __launch_bounds__(256)
void transpose_h3(const float* __restrict__ w0, const float* __restrict__ w1,
                  const float* __restrict__ w2, __half* __restrict__ dst)
{
    __shared__ float t[32][33];
    const int z = blockIdx.z;
    const float* src = (z == 0) ? w0 : (z == 1) ? w1 : w2;
    __half* d = dst + (long long)z * WN3;
    int tx = threadIdx.x, ty = threadIdx.y;
    int x = blockIdx.x * 32 + tx;
    int y0 = blockIdx.y * 32;
    #pragma unroll
    for (int i = 0; i < 32; i += 8)
        t[ty + i][tx] = src[(long long)(y0 + ty + i) * 1536 + x];
    __syncthreads();
    int x2 = blockIdx.y * 32 + tx;
    int y2 = blockIdx.x * 32;
    #pragma unroll
    for (int i = 0; i < 32; i += 8)
        d[(long long)(y2 + ty + i) * 1536 + x2] = __float2half_rn(t[tx][ty + i]);
}

// =======================================================================
// fp16 WMMA NT GEMM body (R9-proven): C = A * B^T, fp32 accum.
// CTA 128x128, 8 warps (2x4), warp tile 64x32. 3-stage cp.async, TK=64.
// EPI 0: fp32 direct store_matrix_sync, padded strides, no guard
// EPI 1: fused QKV (z: 0->Cv(q),1->C1(k),2->C2(vt)); scale only z==0
// EPI 2: ctx: z=(b,h): fp32 out[(b*S+gm)*1536 + h*384 + gn], guarded
// EPI 3: half output, padded row stride ldC, no guard (R)
// BAND: early-exit for R band
// =======================================================================
template<int EPI, bool BAND>
__device__ __forceinline__
void gemm_body(int bx, int by, int bz,
               const __half* __restrict__ A, const __half* __restrict__ B,
               void* __restrict__ Cv,
               int M, int N, int K,
               long long strA, long long strB, long long strC, int ldC,
               float scale, __half* __restrict__ C1, __half* __restrict__ C2)
{
    constexpr int WNv = 32;
    constexpr int NF  = 2;
    constexpr int A_BYTES = BM * LDA * 2;
    constexpr int B_BYTES = BNV * LDA * 2;
    constexpr int STAGE_BYTES = A_BYTES + B_BYTES;   // 36864
    constexpr int LDC = BNV + 4;

    const int m0 = by * BM;
    const int n0 = bx * BNV;

    if (BAND) {
        int mq0 = m0 % Ss;
        int qlo, qhi;
        if (mq0 + (BM - 1) < Ss) { qlo = mq0; qhi = mq0 + BM - 1; }
        else                     { qlo = 0;   qhi = Ss - 1; }
        int lmin = HALFL - qhi, lmax = (Ll - 1) - qlo;
        if (n0 > lmax || n0 + BNV - 1 < lmin) return;
    }

    extern __shared__ char smem[];
    const uint32_t sb = smem_u32(smem);

    const int tid  = threadIdx.x;
    const int warp = tid >> 5;
    const int wm   = warp >> 2;
    const int wn   = warp & 3;
    const int z    = bz;

    A += (long long)z * strA;
    B += (long long)z * strB;
    if (EPI == 1 && z != 0) scale = 1.0f;

    const int nIter = (K + TK - 1) / TK;

    wmma::fragment<wmma::accumulator, 16, 16, 16, float> acc[4][NF];
    #pragma unroll
    for (int i = 0; i < 4; i++)
        #pragma unroll
        for (int j = 0; j < NF; j++)
            wmma::fill_fragment(acc[i][j], 0.0f);

    auto issue_stage = [&](int s) {
        const uint32_t base = sb + (uint32_t)(s % NSTAGE) * STAGE_BYTES;
        const int k0 = s * TK;
        #pragma unroll
        for (int t = 0; t < 4; t++) {
            int idx = tid + t * NTHREADS;
            int r = idx >> 3, c = idx & 7;
            int gm = m0 + r, gk = k0 + c * 8;
            bool p = (gm < M) && (gk < K);
            const __half* src = A + (long long)(p ? gm : 0) * K + (p ? gk : 0);
            cp16s(base + (uint32_t)(r * (LDA * 2) + c * 16), src, p);
        }
        #pragma unroll
        for (int t = 0; t < 4; t++) {
            int idx = tid + t * NTHREADS;
            int r = idx >> 3, c = idx & 7;
            int gn = n0 + r, gk = k0 + c * 8;
            bool p = (gn < N) && (gk < K);
            const __half* src = B + (long long)(p ? gn : 0) * K + (p ? gk : 0);
            cp16s(base + (uint32_t)A_BYTES + (uint32_t)(r * (LDA * 2) + c * 16), src, p);
        }
        cp_commit();
    };

    issue_stage(0);
    issue_stage(1);

    for (int it = 0; it < nIter; ++it) {
        const __half* cA = (const __half*)(smem + (it % NSTAGE) * STAGE_BYTES);
        const __half* cB = (const __half*)(smem + (it % NSTAGE) * STAGE_BYTES + A_BYTES);

        if (it + 1 < nIter) cp_wait1(); else cp_wait0();
        __syncthreads();
        if (it + 2 < nIter) issue_stage(it + 2);

        #pragma unroll
        for (int kk = 0; kk < TK; kk += 16) {
            wmma::fragment<wmma::matrix_a, 16, 16, 16, __half, wmma::row_major> af[4];
            #pragma unroll
            for (int i = 0; i < 4; i++)
                wmma::load_matrix_sync(af[i], cA + (wm * 64 + i * 16) * LDA + kk, LDA);
            wmma::fragment<wmma::matrix_b, 16, 16, 16, __half, wmma::col_major> bf[NF];
            #pragma unroll
            for (int j = 0; j < NF; j++)
                wmma::load_matrix_sync(bf[j], cB + (wn * WNv + j * 16) * LDA + kk, LDA);
            #pragma unroll
            for (int i = 0; i < 4; i++)
                #pragma unroll
                for (int j = 0; j < NF; j++)
                    wmma::mma_sync(acc[i][j], af[i], bf[j], acc[i][j]);
        }
    }

    if (EPI == 0) {
        float* Cg = (float*)Cv + (long long)z * strC;
        #pragma unroll
        for (int i = 0; i < 4; i++) {
            int gm = m0 + wm * 64 + i * 16;
            #pragma unroll
            for (int j = 0; j < NF; j++) {
                int gn = n0 + wn * WNv + j * 16;
                wmma::store_matrix_sync(Cg + (long long)gm * ldC + gn,
                                        acc[i][j], ldC, wmma::mem_row_major);
            }
        }
        return;
    }

    __syncthreads();
    float* shC = (float*)smem;   // [BM][LDC]
    #pragma unroll
    for (int i = 0; i < 4; i++)
        #pragma unroll
        for (int j = 0; j < NF; j++)
            wmma::store_matrix_sync(&shC[(wm * 64 + i * 16) * LDC + (wn * WNv + j * 16)],
                                    acc[i][j], LDC, wmma::mem_row_major);
    __syncthreads();

    if (EPI == 3) {
        __half* Cg = (__half*)Cv;
        #pragma unroll 4
        for (int idx = tid; idx < BM * BNV; idx += NTHREADS) {
            int i = idx >> 7, j = idx & 127;
            Cg[(long long)(m0 + i) * ldC + (n0 + j)] = __float2half_rn(shC[i * LDC + j]);
        }
    } else if (EPI == 1 && z == 2) {
        #pragma unroll 4
        for (int idx = tid; idx < BM * BNV; idx += NTHREADS) {
            int i = idx & (BM - 1), j = idx >> 7;
            int gm = m0 + i, gn = n0 + j;
            if (gm >= M || gn >= N) continue;
            float v = shC[i * LDC + j];
            int b2 = gm / Ss, sP = gm - b2 * Ss;
            int h = gn / HDd, d = gn - h * HDd;
            C2[(((long long)(b2 * Hh + h)) * HDd + d) * Ss + sP] = __float2half_rn(v);
        }
    } else {
        #pragma unroll 4
        for (int idx = tid; idx < BM * BNV; idx += NTHREADS) {
            int i = idx >> 7, j = idx & 127;
            int gm = m0 + i, gn = n0 + j;
            if (gm >= M || gn >= N) continue;
            float v = shC[i * LDC + j] * scale;
            if (EPI == 1) {
                int b2 = gm / Ss, sP = gm - b2 * Ss;
                int h = gn / HDd, d = gn - h * HDd;
                __half hv = __float2half_rn(v);
                long long o = (((long long)(b2 * Hh + h)) * Ss + sP) * HDd + d;
                if (z == 0) ((__half*)Cv)[o] = hv; else C1[o] = hv;
            } else { // EPI == 2
                int b2 = z >> 2, h = z & 3;
                ((float*)Cv)[((long long)b2 * Ss + gm) * (Hh * HDd) + h * HDd + gn] = v;
            }
        }
    }
}

// standalone GEMM kernels
template<int EPI, bool BAND>
__global__ __launch_bounds__(NTHREADS, 2)
void gemm_k(const __half* __restrict__ A, const __half* __restrict__ B,
            void* __restrict__ Cv,
            int M, int N, int K,
            long long strA, long long strB, long long strC, int ldC,
            float scale, __half* __restrict__ C1, __half* __restrict__ C2)
{
    gemm_body<EPI, BAND>(blockIdx.x, blockIdx.y, blockIdx.z,
                         A, B, Cv, M, N, K, strA, strB, strC, ldC, scale, C1, C2);
}

// fused R (banded, EPI3) + scores (EPI0) in one launch: flattened grid
__global__ __launch_bounds__(NTHREADS, 2)
void gemm_rs(const __half* __restrict__ q, const __half* __restrict__ de,
             __half* __restrict__ r,
             const __half* __restrict__ k, float* __restrict__ s)
{
    int i = blockIdx.x;
    if (i < NR_CTAS) {
        gemm_body<3, true>(i % R_GX, i / R_GX, 0,
                           q, de, (void*)r, MQ, Ll, HDd,
                           0, 0, 0, RST, 1.0f, nullptr, nullptr);
    } else {
        int j = i - NR_CTAS;                  // 0 .. 2047
        gemm_body<0, false>(j & 7, (j >> 3) & 7, j >> 6,
                            q, k, (void*)s, Ss, Ss, HDd,
                            (long long)Ss * HDd, (long long)Ss * HDd,
                            (long long)SZSTR, SROW, 1.0f, nullptr, nullptr);
    }
}

// =======================================================================
// bias + softmax: scores[bh,q,k] += R_half[m, k-q+919]; softmax; half probs
// =======================================================================
__global__ __launch_bounds__(256)
void bias_softmax(const float* __restrict__ sc, const __half* __restrict__ R,
                  __half* __restrict__ P)
{
    const int r = blockIdx.x;
    const int bh = r / Ss, q = r - bh * Ss;
    const float* row = sc + (long long)bh * SZSTR + (long long)q * SROW;
    const __half* rrow = R + (long long)r * RST + (HALFL - q);
    __half* prow = P + (long long)r * Ss;

    const int tid = threadIdx.x, lane = tid & 31, wid = tid >> 5;
    __shared__ float wred[8];

    float vals[4];
    float mx = -1e30f;
    #pragma unroll
    for (int i = 0; i < 4; i++) {
        int k = tid + i * 256;
        float v = -1e30f;
        if (k < Ss) v = row[k] + __half2float(rrow[k]);
        vals[i] = v;
        mx = fmaxf(mx, v);
    }
    #pragma unroll
    for (int o = 16; o > 0; o >>= 1) mx = fmaxf(mx, __shfl_xor_sync(0xffffffffu, mx, o));
    if (lane == 0) wred[wid] = mx;
    __syncthreads();
    mx = wred[0];
    #pragma unroll
    for (int w = 1; w < 8; w++) mx = fmaxf(mx, wred[w]);
    __syncthreads();

    float sum = 0.0f;
    #pragma unroll
    for (int i = 0; i < 4; i++) {
        int k = tid + i * 256;
        float e = 0.0f;
        if (k < Ss) e = __expf(vals[i] - mx);
        vals[i] = e;
        sum += e;
    }
    #pragma unroll
    for (int o = 16; o > 0; o >>= 1) sum += __shfl_xor_sync(0xffffffffu, sum, o);
    if (lane == 0) wred[wid] = sum;
    __syncthreads();
    sum = 0.0f;
    #pragma unroll
    for (int w = 0; w < 8; w++) sum += wred[w];

    const float inv = 1.0f / sum;
    #pragma unroll
    for (int i = 0; i < 4; i++) {
        int k = tid + i * 256;
        if (k < Ss) prow[k] = __float2half_rn(vals[i] * inv);
    }
}

// =======================================================================
extern "C" void kernel_launch(void* const* d_in, const int* in_sizes, int n_in,
                              void* d_out, int out_size)
{
    (void)in_sizes; (void)n_in; (void)out_size;
    const float* hs = (const float*)d_in[0];
    const float* wq = (const float*)d_in[1];
    const float* wk = (const float*)d_in[2];
    const float* wv = (const float*)d_in[3];
    const float* de = (const float*)d_in[4];
    float* out = (float*)d_out;

    __half *q, *k, *vt, *p, *hsr, *wt, *der, *r;
    float *s;
    cudaGetSymbolAddress((void**)&q,   g_q);
    cudaGetSymbolAddress((void**)&k,   g_k);
    cudaGetSymbolAddress((void**)&vt,  g_vt);
    cudaGetSymbolAddress((void**)&r,   g_r);
    cudaGetSymbolAddress((void**)&s,   g_s);
    cudaGetSymbolAddress((void**)&p,   g_p);
    cudaGetSymbolAddress((void**)&hsr, g_hs);
    cudaGetSymbolAddress((void**)&wt,  g_wt);
    cudaGetSymbolAddress((void**)&der, g_de);

    const int stage3 = NSTAGE * ((BM + BNV) * LDA * 2);             // 110592
    const int shC    = BM * (BNV + 4) * 4;                          // 67584
    const int smemST = (stage3 > shC) ? stage3 : shC;               // 110592
    cudaFuncSetAttribute((const void*)gemm_k<1, false>, cudaFuncAttributeMaxDynamicSharedMemorySize, smemST);
    cudaFuncSetAttribute((const void*)gemm_rs,          cudaFuncAttributeMaxDynamicSharedMemorySize, smemST);
    cudaFuncSetAttribute((const void*)gemm_k<2, false>, cudaFuncAttributeMaxDynamicSharedMemorySize, smemST);

    const float inv = 1.0f / sqrtf((float)HDd);
    dim3 blk(NTHREADS);

    // 0) prep: fused f2h (hs + de), fused weight transpose
    f2h_copy2<<<512, 256>>>((const float4*)hs, (uint2*)hsr, (Bb * Ss * Dd) / 4,
                            (const float4*)de, (uint2*)der, (Ll * HDd) / 4);
    transpose_h3<<<dim3(48, 48, 3), dim3(32, 8)>>>(wq, wk, wv, wt);

    // 1) fused QKV
    dim3 gA(Dd / BNV, (Bb * Ss + BM - 1) / BM, 3);                  // (12, 58, 3)
    gemm_k<1, false><<<gA, blk, smemST>>>(hsr, wt, q, Bb * Ss, Hh * HDd, Dd,
                                          0, (long long)WN3, 0, 0, inv, k, vt);

    // 2+3) R (banded) and scores fused into ONE launch (independent work)
    gemm_rs<<<NR_CTAS + NS_CTAS, blk, smemST>>>(q, der, r, k, s);

    // 4) bias + softmax -> half probs
    bias_softmax<<<MQ, 256>>>(s, r, p);

    // 5) ctx = P @ Vt^T per bh -> fp32 (B,S,H*HD)
    dim3 gO(HDd / BNV, (Ss + BM - 1) / BM, BH);                     // (3, 8, 32)
    gemm_k<2, false><<<gO, blk, smemST>>>(p, vt, out, Ss, HDd, Ss,
                                          (long long)Ss * Ss, (long long)HDd * Ss,
                                          0, 0, 1.0f, nullptr, nullptr);
}